// round 11
// baseline (speedup 1.0000x reference)
#include <cuda_runtime.h>

// Problem constants (fixed by the dataset)
#define Nn  64      // waveguides
#define Dd  8       // decomp
#define Ww  128     // wavelengths
#define Bb  512     // batch
#define Kk  64      // chain depth
#define Sd  65      // Ex row stride (float2): conflict-free 16-lane phases

// Smem (float2): ExA[64*Sd] + ExB[64*Sd] + tS0[64] + tS1[64]
#define SMEM_F2    (2 * Nn * Sd + 2 * Nn)
#define SMEM_BYTES (SMEM_F2 * (int)sizeof(float2))   // 67584 B

typedef unsigned long long u64t;

// ---------------------------------------------------------------------------
__device__ __forceinline__ float gldf(const float* __restrict__ p,
                                      long long i, long long n)
{
    return (p && i >= 0 && i < n) ? p[i] : 0.0f;
}

__device__ __forceinline__ void safe_sincos(float a, float* s, float* c)
{
    float n = rintf(a * 0.15915494309189535f);
    float r = fmaf(n, -6.2831855f, a);
    r = fmaf(n, 1.7484556e-7f, r);
    sincosf(r, s, c);
}

// ---- packed f32x2 helpers (only fma/add, both validated on sm_103a) -------
__device__ __forceinline__ u64t pk2(float x, float y)
{ u64t r; asm("mov.b64 %0, {%1, %2};" : "=l"(r) : "f"(x), "f"(y)); return r; }

__device__ __forceinline__ void up2(u64t a, float& x, float& y)
{ asm("mov.b64 {%0, %1}, %2;" : "=f"(x), "=f"(y) : "l"(a)); }

__device__ __forceinline__ u64t padd(u64t a, u64t b)
{ u64t r; asm("add.rn.f32x2 %0, %1, %2;" : "=l"(r) : "l"(a), "l"(b)); return r; }

__device__ __forceinline__ u64t pfma(u64t a, u64t b, u64t c)
{ u64t r; asm("fma.rn.f32x2 %0, %1, %2, %3;" : "=l"(r)
              : "l"(a), "l"(b), "l"(c)); return r; }

__device__ __forceinline__ void ffma2(u64t& acc, u64t a, u64t b)
{ asm("fma.rn.f32x2 %0, %1, %2, %0;" : "+l"(acc) : "l"(a), "l"(b)); }

// scalar complex mul (bit-identical to prior rounds' cmul)
__device__ __forceinline__ float2 cmulf(float ax, float ay, float2 w)
{
    float t1 = ay * w.y;
    float re = fmaf(ax, w.x, -t1);
    float t2 = ay * w.x;
    float im = fmaf(ax, w.y, t2);
    return make_float2(re, im);
}

// ---------------------------------------------------------------------------
__global__ void pic_probe(float* __restrict__ outf, long long n)
{
    long long i = (long long)blockIdx.x * blockDim.x + threadIdx.x;
    if (i < n) outf[i] = 0.0f;
}

// ---------------------------------------------------------------------------
// One CTA per (d,w), 256 threads. Thread (q=tid>>6, row=tid&63) holds
// X[e] = M[row, q+4e] in registers across all 64 k-steps.
// Per k: stages A,B thread-local (packed bflys + scalar twiddles),
// one smem exchange (double-buffered Ex), stage C outputs land back in X.
// Then M -> SoA planes, and the validated FFMA2 real-part apply.
// ---------------------------------------------------------------------------
__global__ void __launch_bounds__(256, 2)
pic_fused(const float* __restrict__ vals, long long nv,
          const float* __restrict__ wls,  long long nw,
          const float* __restrict__ xr,   long long nxr,
          const float* __restrict__ xi,   long long nxi,
          int xstride,
          float*       __restrict__ outf, long long nof)
{
    extern __shared__ float2 sh[];
    float2* ExA = sh;                       // [64*Sd]
    float2* ExB = sh + Nn * Sd;             // [64*Sd]
    float2* tS0 = sh + 2 * Nn * Sd;         // [64]
    float2* tS1 = tS0 + Nn;                 // [64]

    const int w   = blockIdx.x;
    const int d   = blockIdx.y;
    const int tid = threadIdx.x;
    const int q   = tid >> 6;               // 0..3
    const int row = tid & 63;
    const float wl = gldf(wls, w, nw);
    const u64t NEG1 = pk2(-1.0f, -1.0f);

    // Twiddles (per-thread constants, reference-matching f32 angles)
    const float CANG = -0.09817477042468103f;   // fl(-2*pi/64)
    float2 wA[4][3], wB[3];
    #pragma unroll
    for (int e0 = 0; e0 < 4; e0++)
        #pragma unroll
        for (int r = 1; r <= 3; r++) {
            float s0, c0;
            safe_sincos(CANG * (float)((q + 4 * e0) * r), &s0, &c0);
            wA[e0][r - 1] = make_float2(c0, s0);
        }
    #pragma unroll
    for (int s1 = 1; s1 <= 3; s1++) {
        float s0, c0;
        safe_sincos(CANG * (float)(4 * q * s1), &s0, &c0);
        wB[s1 - 1] = make_float2(c0, s0);
    }

    // M = Identity, register-resident: X[e] = M[row, q+4e]
    u64t Xp[16];
    #pragma unroll
    for (int e = 0; e < 16; e++)
        Xp[e] = pk2((q + 4 * e == row) ? 1.0f : 0.0f, 0.0f);

    // =================== Phase A: build (64 k-steps) ======================
    for (int k = 0; k < Kk; ++k) {
        float2* Ex  = (k & 1) ? ExB : ExA;
        float2* tSb = (k & 1) ? tS1 : tS0;

        // Ring response 0.125*t[n] (threads 0..63), reference f32 op order
        if (tid < Nn) {
            const int n = tid;
            float Ln  = __fmul_rn(31.415926535897931f,
                        __fadd_rn(1.0f, __fmul_rn(0.01f, (float)n)));
            float v   = gldf(vals, (long long)(k * Dd + d) * Nn + n, nv);
            float phi = __fadd_rn(
                __fmul_rn(15.079644737231007f, __fdiv_rn(Ln, wl)),
                __fmul_rn(6.2831853071795862f, v));
            float s0, c0;
            safe_sincos(phi, &s0, &c0);
            float nr = __fsub_rn(0.95f, __fmul_rn(0.99f, c0));
            float ni = -__fmul_rn(0.99f, s0);
            float dr = __fsub_rn(1.0f, __fmul_rn(0.9405f, c0));
            float di = -__fmul_rn(0.9405f, s0);
            float inv = 1.0f / (dr * dr + di * di);
            tSb[n] = make_float2(0.125f * ((nr * dr + ni * di) * inv),
                                 0.125f * ((ni * dr - nr * di) * inv));
        }

        // -------- Stage A (stride 16), thread-local, packed bflys --------
        u64t Yp[16];
        #pragma unroll
        for (int e0 = 0; e0 < 4; e0++) {
            u64t a = Xp[e0], b = Xp[e0 + 4], c = Xp[e0 + 8], dd2 = Xp[e0 + 12];
            u64t t0 = padd(a, c),   t1 = pfma(c, NEG1, a);
            u64t t2 = padd(b, dd2), t3 = pfma(dd2, NEG1, b);
            Yp[e0]  = padd(t0, t2);                       // o0 (no twiddle)
            u64t o2 = pfma(t2, NEG1, t0);
            float x1, y1, x3, y3, x2, y2;
            up2(t1, x1, y1); up2(t3, x3, y3);
            float2 r1 = cmulf(x1 + y3, y1 - x3, wA[e0][0]);   // o1*w
            up2(o2, x2, y2);
            float2 r2 = cmulf(x2, y2, wA[e0][1]);             // o2*w
            float2 r3 = cmulf(x1 - y3, y1 + x3, wA[e0][2]);   // o3*w
            Yp[4 + e0]  = pk2(r1.x, r1.y);
            Yp[8 + e0]  = pk2(r2.x, r2.y);
            Yp[12 + e0] = pk2(r3.x, r3.y);
        }

        // -------- Stage B (stride 4) -> Ex exchange ----------------------
        #pragma unroll
        for (int r = 0; r < 4; r++) {
            u64t a = Yp[4 * r], b = Yp[4 * r + 1];
            u64t c = Yp[4 * r + 2], dd2 = Yp[4 * r + 3];
            u64t t0 = padd(a, c),   t1 = pfma(c, NEG1, a);
            u64t t2 = padd(b, dd2), t3 = pfma(dd2, NEG1, b);
            u64t o0 = padd(t0, t2);
            u64t o2 = pfma(t2, NEG1, t0);
            float x1, y1, x3, y3, x2, y2;
            up2(t1, x1, y1); up2(t3, x3, y3);
            float2 r1 = cmulf(x1 + y3, y1 - x3, wB[0]);
            up2(o2, x2, y2);
            float2 r2 = cmulf(x2, y2, wB[1]);
            float2 r3 = cmulf(x1 - y3, y1 + x3, wB[2]);
            int base = row * Sd + q;
            *(u64t*)&Ex[base + 4 * r]      = o0;      // s=0
            Ex[base + 16 + 4 * r]          = r1;      // s=1
            Ex[base + 32 + 4 * r]          = r2;      // s=2
            Ex[base + 48 + 4 * r]          = r3;      // s=3
        }
        __syncthreads();

        // -------- Stage C (stride 1, r=q) + diag(t) -> back to X ---------
        #pragma unroll
        for (int s = 0; s < 4; s++) {
            int base = row * Sd + 16 * s + 4 * q;
            u64t a   = *(u64t*)&Ex[base + 0];
            u64t b   = *(u64t*)&Ex[base + 1];
            u64t c   = *(u64t*)&Ex[base + 2];
            u64t dd2 = *(u64t*)&Ex[base + 3];
            u64t t0 = padd(a, c),   t1 = pfma(c, NEG1, a);
            u64t t2 = padd(b, dd2), t3 = pfma(dd2, NEG1, b);
            u64t o0 = padd(t0, t2);
            u64t o2 = pfma(t2, NEG1, t0);
            float x0, y0, x1, y1, x2, y2, x3, y3;
            up2(o0, x0, y0);
            up2(t1, x1, y1); up2(t3, x3, y3);
            up2(o2, x2, y2);
            int nb = 4 * s + q;
            float2 v0 = cmulf(x0, y0,               tSb[nb]);        // tau=0
            float2 v1 = cmulf(x1 + y3, y1 - x3,     tSb[nb + 16]);   // tau=1
            float2 v2 = cmulf(x2, y2,               tSb[nb + 32]);   // tau=2
            float2 v3 = cmulf(x1 - y3, y1 + x3,     tSb[nb + 48]);   // tau=3
            Xp[s]      = pk2(v0.x, v0.y);
            Xp[4 + s]  = pk2(v1.x, v1.y);
            Xp[8 + s]  = pk2(v2.x, v2.y);
            Xp[12 + s] = pk2(v3.x, v3.y);
        }
        // no trailing sync: Ex double-buffered, tS double-buffered
    }
    __syncthreads();   // all stage-C reads done before planes overwrite ExB

    // ============ M -> SoA planes (Mre, -Mim), stride 66 floats ===========
    float* shf = (float*)sh;
    float* Xr  = shf;                       // [4096] over ExA
    float* Xi  = shf + 4096;                // [4096]
    float* Mre = shf + 2 * Nn * Sd;         // float ofs 8320, 4224 floats
    float* Mim = Mre + Nn * 66;             // 4224 floats (pre-negated)

    #pragma unroll
    for (int e = 0; e < 16; e++) {
        int n = q + 4 * e;
        float x, y; up2(Xp[e], x, y);
        Mre[row * 66 + n] =  x;
        Mim[row * 66 + n] = -y;
    }
    __syncthreads();

    // =================== Phase B: apply (real part only) ==================
    const int tb = tid >> 4;            // batch rows {4tb..4tb+3}
    const int ti = tid & 15;            // output cols {ti,+16,+32,+48}

    for (int bt = 0; bt < Bb / 64; ++bt) {
        for (int idx = tid; idx < Nn * Nn; idx += 256) {
            int r = idx >> 6, j = idx & 63;
            long long b = (long long)bt * 64 + r;
            long long g = ((b * Dd + d) * Ww + w) * Nn + j;
            Xr[r * 64 + j] = gldf(xr, g * xstride, nxr);
            Xi[r * 64 + j] = gldf(xi, g * xstride, nxi);
        }
        __syncthreads();

        u64t acc[4][4];
        #pragma unroll
        for (int r = 0; r < 4; r++)
            #pragma unroll
            for (int c = 0; c < 4; c++)
                acc[r][c] = 0ull;

        #pragma unroll 4
        for (int jp = 0; jp < Nn / 2; ++jp) {
            u64t xr2[4], xi2[4], mr2[4], mi2[4];
            #pragma unroll
            for (int r = 0; r < 4; r++) {
                xr2[r] = *(const u64t*)(Xr + (tb * 4 + r) * 64 + 2 * jp);
                xi2[r] = *(const u64t*)(Xi + (tb * 4 + r) * 64 + 2 * jp);
            }
            #pragma unroll
            for (int c = 0; c < 4; c++) {
                mr2[c] = *(const u64t*)(Mre + (ti + 16 * c) * 66 + 2 * jp);
                mi2[c] = *(const u64t*)(Mim + (ti + 16 * c) * 66 + 2 * jp);
            }
            #pragma unroll
            for (int r = 0; r < 4; r++)
                #pragma unroll
                for (int c = 0; c < 4; c++) {
                    ffma2(acc[r][c], xr2[r], mr2[c]);
                    ffma2(acc[r][c], xi2[r], mi2[c]);   // Mim pre-negated
                }
        }

        #pragma unroll
        for (int r = 0; r < 4; r++)
            #pragma unroll
            for (int c = 0; c < 4; c++) {
                float lo, hi; up2(acc[r][c], lo, hi);
                float re = lo + hi;
                long long b = (long long)bt * 64 + tb * 4 + r;
                int i = ti + 16 * c;
                long long g = ((b * Dd + d) * Ww + w) * Nn + i;
                if (g < nof) outf[g] = re;
            }
        __syncthreads();
    }
}

// ---------------------------------------------------------------------------
extern "C" void kernel_launch(void* const* d_in, const int* in_sizes, int n_in,
                              void* d_out, int out_size)
{
    const long long NX = (long long)Bb * Dd * Ww * Nn;   // 33,554,432
    const long long NV = (long long)Kk * Dd * Nn;        // 32,768
    const long long NW = Ww;                             // 128

    const float *x0 = 0, *x1 = 0, *vals = 0, *wls = 0;
    long long nx0 = 0, nx1 = 0, nv = 0, nw = 0;
    int xcomplex = 0;

    for (int pass = 0; pass < 2; ++pass) {
        long long mul = (pass == 0) ? 1 : 4;
        x0 = x1 = vals = wls = 0; nx0 = nx1 = nv = nw = 0; xcomplex = 0;
        int nxbuf = 0;
        for (int i = 0; i < n_in; i++) {
            long long s = (long long)in_sizes[i];
            const float* p = (const float*)d_in[i];
            if (!p) continue;
            if (s == NX * mul) {
                if (nxbuf == 0) { x0 = p; nx0 = NX; nxbuf = 1; }
                else if (nxbuf == 1) { x1 = p; nx1 = NX; nxbuf = 2; }
            } else if (s == 2 * NX * mul) {
                x0 = p; nx0 = 2 * NX; nxbuf = 2; xcomplex = 1;
            } else if (s == NV * mul) { if (!vals) { vals = p; nv = NV; } }
            else if (s == NW * mul)   { if (!wls)  { wls  = p; nw = NW; } }
        }
        if (nxbuf == 1 && vals && wls) {
            xcomplex = 1; nx0 = 2 * NX; x1 = 0; nxbuf = 2;
        }
        if (nxbuf == 2 && vals && wls) break;
        x0 = 0;
    }

    if (!(x0 && vals && wls) || !d_out) {
        long long n = (out_size > 4) ? (long long)out_size / 4 : 1;
        pic_probe<<<(unsigned)((n + 255) / 256), 256>>>((float*)d_out, n);
        return;
    }

    // d_out = out_size float32 (real part) — established R8.
    long long n_floats = ((long long)out_size < NX) ? (long long)out_size : NX;

    const float* xrp; const float* xip; long long nxr, nxi; int xstride;
    if (xcomplex) { xrp = x0; nxr = nx0; xip = x0 + 1; nxi = nx0 - 1; xstride = 2; }
    else          { xrp = x0; nxr = nx0; xip = x1;     nxi = nx1;     xstride = 1; }

    cudaFuncSetAttribute(pic_fused, cudaFuncAttributeMaxDynamicSharedMemorySize,
                         SMEM_BYTES);

    dim3 grid(Ww, Dd);
    pic_fused<<<grid, 256, SMEM_BYTES>>>(vals, nv, wls, nw,
                                         xrp, nxr, xip, nxi, xstride,
                                         (float*)d_out, n_floats);
}

// round 12
// speedup vs baseline: 1.5026x; 1.5026x over previous
#include <cuda_runtime.h>

// Problem constants (fixed by the dataset)
#define Nn  64      // waveguides
#define Dd  8       // decomp
#define Ww  128     // wavelengths
#define Bb  512     // batch
#define Kk  64      // chain depth
#define Sd  65      // Ex row stride (float2): conflict-free 16-lane phases

// Smem (float2): ExA[64*Sd] + ExB[64*Sd] + tS0[64] + tS1[64]
#define SMEM_F2    (2 * Nn * Sd + 2 * Nn)
#define SMEM_BYTES (SMEM_F2 * (int)sizeof(float2))   // 67584 B

typedef unsigned long long u64t;

// ---------------------------------------------------------------------------
__device__ __forceinline__ float gldf(const float* __restrict__ p,
                                      long long i, long long n)
{
    return (p && i >= 0 && i < n) ? p[i] : 0.0f;
}

__device__ __forceinline__ void safe_sincos(float a, float* s, float* c)
{
    float n = rintf(a * 0.15915494309189535f);
    float r = fmaf(n, -6.2831855f, a);
    r = fmaf(n, 1.7484556e-7f, r);
    sincosf(r, s, c);
}

__device__ __forceinline__ float2 cmul(float2 a, float2 b)
{
    return make_float2(fmaf(a.x, b.x, -a.y * b.y),
                       fmaf(a.x, b.y,  a.y * b.x));
}

// Packed dual-lane FMA for the APPLY phase only (validated fast in R10)
__device__ __forceinline__ void ffma2(u64t& acc, u64t a, u64t b)
{ asm("fma.rn.f32x2 %0, %1, %2, %0;" : "+l"(acc) : "l"(a), "l"(b)); }

// Radix-4 DIF butterfly (plain float2 — compiler-scheduled, R10-validated)
__device__ __forceinline__ void bfly4(float2 a, float2 b, float2 c, float2 d,
                                      float2& o0, float2& o1,
                                      float2& o2, float2& o3)
{
    float t0x = a.x + c.x, t0y = a.y + c.y;
    float t1x = a.x - c.x, t1y = a.y - c.y;
    float t2x = b.x + d.x, t2y = b.y + d.y;
    float t3x = b.x - d.x, t3y = b.y - d.y;
    o0 = make_float2(t0x + t2x, t0y + t2y);
    o2 = make_float2(t0x - t2x, t0y - t2y);
    o1 = make_float2(t1x + t3y, t1y - t3x);
    o3 = make_float2(t1x - t3y, t1y + t3x);
}

// ---------------------------------------------------------------------------
__global__ void pic_probe(float* __restrict__ outf, long long n)
{
    long long i = (long long)blockIdx.x * blockDim.x + threadIdx.x;
    if (i < n) outf[i] = 0.0f;
}

// ---------------------------------------------------------------------------
// One CTA per (d,w), 256 threads. Thread (q=tid>>6, row=tid&63) holds
// X[e] = M[row, q+4e] in registers across all 64 k-steps.
// Per k: stages A,B thread-local; one double-buffered smem exchange;
// stage C assigned r=q so outputs n = q+4e land back in this thread's X.
// (Index algebra validated by R11's bit-identical pass.)
// Then M -> SoA planes and the R10-validated FFMA2 real-part apply.
// ---------------------------------------------------------------------------
__global__ void __launch_bounds__(256, 2)
pic_fused(const float* __restrict__ vals, long long nv,
          const float* __restrict__ wls,  long long nw,
          const float* __restrict__ xr,   long long nxr,
          const float* __restrict__ xi,   long long nxi,
          int xstride,
          float*       __restrict__ outf, long long nof)
{
    extern __shared__ float2 sh[];
    float2* ExA = sh;                       // [64*Sd]
    float2* ExB = sh + Nn * Sd;             // [64*Sd]
    float2* tS0 = sh + 2 * Nn * Sd;         // [64]
    float2* tS1 = tS0 + Nn;                 // [64]

    const int w   = blockIdx.x;
    const int d   = blockIdx.y;
    const int tid = threadIdx.x;
    const int q   = tid >> 6;               // 0..3
    const int row = tid & 63;
    const float wl = gldf(wls, w, nw);

    // Twiddles (per-thread constants, reference-matching f32 angles)
    const float CANG = -0.09817477042468103f;   // fl(-2*pi/64)
    float2 wA[4][3], wB[3];
    #pragma unroll
    for (int e0 = 0; e0 < 4; e0++)
        #pragma unroll
        for (int r = 1; r <= 3; r++) {
            float s0, c0;
            safe_sincos(CANG * (float)((q + 4 * e0) * r), &s0, &c0);
            wA[e0][r - 1] = make_float2(c0, s0);
        }
    #pragma unroll
    for (int s1 = 1; s1 <= 3; s1++) {
        float s0, c0;
        safe_sincos(CANG * (float)(4 * q * s1), &s0, &c0);
        wB[s1 - 1] = make_float2(c0, s0);
    }

    // M = Identity, register-resident: X[e] = M[row, q+4e]
    float2 X[16];
    #pragma unroll
    for (int e = 0; e < 16; e++)
        X[e] = make_float2((q + 4 * e == row) ? 1.0f : 0.0f, 0.0f);

    // =================== Phase A: build (64 k-steps) ======================
    for (int k = 0; k < Kk; ++k) {
        float2* Ex  = (k & 1) ? ExB : ExA;
        float2* tSb = (k & 1) ? tS1 : tS0;

        // Ring response 0.125*t[n] (threads 0..63), reference f32 op order
        if (tid < Nn) {
            const int n = tid;
            float Ln  = __fmul_rn(31.415926535897931f,
                        __fadd_rn(1.0f, __fmul_rn(0.01f, (float)n)));
            float v   = gldf(vals, (long long)(k * Dd + d) * Nn + n, nv);
            float phi = __fadd_rn(
                __fmul_rn(15.079644737231007f, __fdiv_rn(Ln, wl)),
                __fmul_rn(6.2831853071795862f, v));
            float s0, c0;
            safe_sincos(phi, &s0, &c0);
            float nr = __fsub_rn(0.95f, __fmul_rn(0.99f, c0));
            float ni = -__fmul_rn(0.99f, s0);
            float dr = __fsub_rn(1.0f, __fmul_rn(0.9405f, c0));
            float di = -__fmul_rn(0.9405f, s0);
            float inv = 1.0f / (dr * dr + di * di);
            tSb[n] = make_float2(0.125f * ((nr * dr + ni * di) * inv),
                                 0.125f * ((ni * dr - nr * di) * inv));
        }

        // -------- Stage A (stride 16), thread-local ----------------------
        float2 Y[16];
        #pragma unroll
        for (int e0 = 0; e0 < 4; e0++) {
            float2 o0, o1, o2, o3;
            bfly4(X[e0], X[e0 + 4], X[e0 + 8], X[e0 + 12], o0, o1, o2, o3);
            Y[e0]      = o0;
            Y[4 + e0]  = cmul(o1, wA[e0][0]);
            Y[8 + e0]  = cmul(o2, wA[e0][1]);
            Y[12 + e0] = cmul(o3, wA[e0][2]);
        }

        // -------- Stage B (stride 4) -> Ex exchange ----------------------
        // Slot for z_{r,s}[u=q] is 4*(4s + r) + q.
        #pragma unroll
        for (int r = 0; r < 4; r++) {
            float2 o0, o1, o2, o3;
            bfly4(Y[4 * r + 0], Y[4 * r + 1], Y[4 * r + 2], Y[4 * r + 3],
                  o0, o1, o2, o3);
            int base = row * Sd + q;
            Ex[base + 4 * r]      = o0;                 // s=0
            Ex[base + 16 + 4 * r] = cmul(o1, wB[0]);    // s=1
            Ex[base + 32 + 4 * r] = cmul(o2, wB[1]);    // s=2
            Ex[base + 48 + 4 * r] = cmul(o3, wB[2]);    // s=3
        }
        __syncthreads();

        // -------- Stage C (stride 1): thread handles r=q, loops s --------
        // Reads slots 4*(4s+q)+u = 16s+4q+u; outputs n = 16*tau + 4s + q
        // -> e = (n-q)/4 = 4*tau + s: this thread's own X slots.
        #pragma unroll
        for (int s = 0; s < 4; s++) {
            int base = row * Sd + 16 * s + 4 * q;
            float2 o0, o1, o2, o3;
            bfly4(Ex[base + 0], Ex[base + 1], Ex[base + 2], Ex[base + 3],
                  o0, o1, o2, o3);
            int nb = 4 * s + q;
            X[s]      = cmul(o0, tSb[nb]);          // tau=0
            X[4 + s]  = cmul(o1, tSb[nb + 16]);     // tau=1
            X[8 + s]  = cmul(o2, tSb[nb + 32]);     // tau=2
            X[12 + s] = cmul(o3, tSb[nb + 48]);     // tau=3
        }
        // no trailing sync: Ex and tS double-buffered
    }
    __syncthreads();   // all stage-C reads done before planes overwrite smem

    // ============ M -> SoA planes (Mre, -Mim), stride 66 floats ===========
    float* shf = (float*)sh;
    float* Xr  = shf;                       // [4096] over ExA
    float* Xi  = shf + 4096;                // [4096]
    float* Mre = shf + 2 * Nn * Sd;         // float ofs 8320, 4224 floats
    float* Mim = Mre + Nn * 66;             // 4224 floats (pre-negated)

    #pragma unroll
    for (int e = 0; e < 16; e++) {
        int n = q + 4 * e;
        Mre[row * 66 + n] =  X[e].x;
        Mim[row * 66 + n] = -X[e].y;
    }
    __syncthreads();

    // =================== Phase B: apply (real part only) ==================
    const int tb = tid >> 4;            // batch rows {4tb..4tb+3}
    const int ti = tid & 15;            // output cols {ti,+16,+32,+48}

    for (int bt = 0; bt < Bb / 64; ++bt) {
        for (int idx = tid; idx < Nn * Nn; idx += 256) {
            int r = idx >> 6, j = idx & 63;
            long long b = (long long)bt * 64 + r;
            long long g = ((b * Dd + d) * Ww + w) * Nn + j;
            Xr[r * 64 + j] = gldf(xr, g * xstride, nxr);
            Xi[r * 64 + j] = gldf(xi, g * xstride, nxi);
        }
        __syncthreads();

        u64t acc[4][4];
        #pragma unroll
        for (int r = 0; r < 4; r++)
            #pragma unroll
            for (int c = 0; c < 4; c++)
                acc[r][c] = 0ull;

        #pragma unroll 4
        for (int jp = 0; jp < Nn / 2; ++jp) {
            u64t xr2[4], xi2[4], mr2[4], mi2[4];
            #pragma unroll
            for (int r = 0; r < 4; r++) {
                xr2[r] = *(const u64t*)(Xr + (tb * 4 + r) * 64 + 2 * jp);
                xi2[r] = *(const u64t*)(Xi + (tb * 4 + r) * 64 + 2 * jp);
            }
            #pragma unroll
            for (int c = 0; c < 4; c++) {
                mr2[c] = *(const u64t*)(Mre + (ti + 16 * c) * 66 + 2 * jp);
                mi2[c] = *(const u64t*)(Mim + (ti + 16 * c) * 66 + 2 * jp);
            }
            #pragma unroll
            for (int r = 0; r < 4; r++)
                #pragma unroll
                for (int c = 0; c < 4; c++) {
                    ffma2(acc[r][c], xr2[r], mr2[c]);
                    ffma2(acc[r][c], xi2[r], mi2[c]);   // Mim pre-negated
                }
        }

        #pragma unroll
        for (int r = 0; r < 4; r++)
            #pragma unroll
            for (int c = 0; c < 4; c++) {
                float lo = __uint_as_float((unsigned)(acc[r][c] & 0xffffffffu));
                float hi = __uint_as_float((unsigned)(acc[r][c] >> 32));
                float re = lo + hi;
                long long b = (long long)bt * 64 + tb * 4 + r;
                int i = ti + 16 * c;
                long long g = ((b * Dd + d) * Ww + w) * Nn + i;
                if (g < nof) outf[g] = re;
            }
        __syncthreads();
    }
}

// ---------------------------------------------------------------------------
extern "C" void kernel_launch(void* const* d_in, const int* in_sizes, int n_in,
                              void* d_out, int out_size)
{
    const long long NX = (long long)Bb * Dd * Ww * Nn;   // 33,554,432
    const long long NV = (long long)Kk * Dd * Nn;        // 32,768
    const long long NW = Ww;                             // 128

    const float *x0 = 0, *x1 = 0, *vals = 0, *wls = 0;
    long long nx0 = 0, nx1 = 0, nv = 0, nw = 0;
    int xcomplex = 0;

    for (int pass = 0; pass < 2; ++pass) {
        long long mul = (pass == 0) ? 1 : 4;
        x0 = x1 = vals = wls = 0; nx0 = nx1 = nv = nw = 0; xcomplex = 0;
        int nxbuf = 0;
        for (int i = 0; i < n_in; i++) {
            long long s = (long long)in_sizes[i];
            const float* p = (const float*)d_in[i];
            if (!p) continue;
            if (s == NX * mul) {
                if (nxbuf == 0) { x0 = p; nx0 = NX; nxbuf = 1; }
                else if (nxbuf == 1) { x1 = p; nx1 = NX; nxbuf = 2; }
            } else if (s == 2 * NX * mul) {
                x0 = p; nx0 = 2 * NX; nxbuf = 2; xcomplex = 1;
            } else if (s == NV * mul) { if (!vals) { vals = p; nv = NV; } }
            else if (s == NW * mul)   { if (!wls)  { wls  = p; nw = NW; } }
        }
        if (nxbuf == 1 && vals && wls) {
            xcomplex = 1; nx0 = 2 * NX; x1 = 0; nxbuf = 2;
        }
        if (nxbuf == 2 && vals && wls) break;
        x0 = 0;
    }

    if (!(x0 && vals && wls) || !d_out) {
        long long n = (out_size > 4) ? (long long)out_size / 4 : 1;
        pic_probe<<<(unsigned)((n + 255) / 256), 256>>>((float*)d_out, n);
        return;
    }

    // d_out = out_size float32 (real part) — established R8.
    long long n_floats = ((long long)out_size < NX) ? (long long)out_size : NX;

    const float* xrp; const float* xip; long long nxr, nxi; int xstride;
    if (xcomplex) { xrp = x0; nxr = nx0; xip = x0 + 1; nxi = nx0 - 1; xstride = 2; }
    else          { xrp = x0; nxr = nx0; xip = x1;     nxi = nx1;     xstride = 1; }

    cudaFuncSetAttribute(pic_fused, cudaFuncAttributeMaxDynamicSharedMemorySize,
                         SMEM_BYTES);

    dim3 grid(Ww, Dd);
    pic_fused<<<grid, 256, SMEM_BYTES>>>(vals, nv, wls, nw,
                                         xrp, nxr, xip, nxi, xstride,
                                         (float*)d_out, n_floats);
}

// round 13
// speedup vs baseline: 1.6955x; 1.1284x over previous
#include <cuda_runtime.h>

// Problem constants (fixed by the dataset)
#define Nn  64      // waveguides
#define Dd  8       // decomp
#define Ww  128     // wavelengths
#define Bb  512     // batch
#define Kk  64      // chain depth
#define Sd  65      // Ex row stride (float2): conflict-free 16-lane phases

// Smem layout (float2 units):
//   phase A: ExA [0,4160) + ExB [4160,8320) + tS_all [8320,12416)
//   phase B: Xr/Xi [0,8192) (128x64 floats each) + planes [8320,12544)
#define SMEM_F2    12544
#define SMEM_BYTES (SMEM_F2 * (int)sizeof(float2))   // 100352 B

typedef unsigned long long u64t;

// ---------------------------------------------------------------------------
__device__ __forceinline__ float gldf(const float* __restrict__ p,
                                      long long i, long long n)
{
    return (p && i >= 0 && i < n) ? p[i] : 0.0f;
}

__device__ __forceinline__ void safe_sincos(float a, float* s, float* c)
{
    float n = rintf(a * 0.15915494309189535f);
    float r = fmaf(n, -6.2831855f, a);
    r = fmaf(n, 1.7484556e-7f, r);
    sincosf(r, s, c);
}

__device__ __forceinline__ float2 cmul(float2 a, float2 b)
{
    return make_float2(fmaf(a.x, b.x, -a.y * b.y),
                       fmaf(a.x, b.y,  a.y * b.x));
}

// Packed dual-lane FMA for the APPLY phase only (validated in R10/R12)
__device__ __forceinline__ void ffma2(u64t& acc, u64t a, u64t b)
{ asm("fma.rn.f32x2 %0, %1, %2, %0;" : "+l"(acc) : "l"(a), "l"(b)); }

// Radix-4 DIF butterfly (plain float2 — R10/R12-validated codegen)
__device__ __forceinline__ void bfly4(float2 a, float2 b, float2 c, float2 d,
                                      float2& o0, float2& o1,
                                      float2& o2, float2& o3)
{
    float t0x = a.x + c.x, t0y = a.y + c.y;
    float t1x = a.x - c.x, t1y = a.y - c.y;
    float t2x = b.x + d.x, t2y = b.y + d.y;
    float t3x = b.x - d.x, t3y = b.y - d.y;
    o0 = make_float2(t0x + t2x, t0y + t2y);
    o2 = make_float2(t0x - t2x, t0y - t2y);
    o1 = make_float2(t1x + t3y, t1y - t3x);
    o3 = make_float2(t1x - t3y, t1y + t3x);
}

// ---------------------------------------------------------------------------
__global__ void pic_probe(float* __restrict__ outf, long long n)
{
    long long i = (long long)blockIdx.x * blockDim.x + threadIdx.x;
    if (i < n) outf[i] = 0.0f;
}

// ---------------------------------------------------------------------------
// One CTA per (d,w), 256 threads.
// Phase A (R12-validated): thread (q=tid>>6,row=tid&63) holds X[e]=M[row,q+4e]
// in registers across 64 k-steps; 1 double-buffered smem exchange + 1 sync/k.
// t for ALL k precomputed once into tS_all (warp-broadcast reads in stage C).
// Phase B: real-part apply, 8b x 4i register tile, 128-row batch tiles.
// ---------------------------------------------------------------------------
__global__ void __launch_bounds__(256, 2)
pic_fused(const float* __restrict__ vals, long long nv,
          const float* __restrict__ wls,  long long nw,
          const float* __restrict__ xr,   long long nxr,
          const float* __restrict__ xi,   long long nxi,
          int xstride,
          float*       __restrict__ outf, long long nof)
{
    extern __shared__ float2 sh[];
    float2* ExA    = sh;                    // [4160)
    float2* ExB    = sh + Nn * Sd;          // [4160)
    float2* tS_all = sh + 2 * Nn * Sd;      // [4096): tS_all[k*64+n]

    const int w   = blockIdx.x;
    const int d   = blockIdx.y;
    const int tid = threadIdx.x;
    const int q   = tid >> 6;               // 0..3
    const int row = tid & 63;
    const float wl = gldf(wls, w, nw);

    // ---- Precompute 0.125*t_k[n] for ALL (k,n): 16 entries/thread --------
    for (int idx = tid; idx < Kk * Nn; idx += 256) {
        int k = idx >> 6, n = idx & 63;
        float Ln  = __fmul_rn(31.415926535897931f,
                    __fadd_rn(1.0f, __fmul_rn(0.01f, (float)n)));
        float v   = gldf(vals, (long long)(k * Dd + d) * Nn + n, nv);
        float phi = __fadd_rn(
            __fmul_rn(15.079644737231007f, __fdiv_rn(Ln, wl)),
            __fmul_rn(6.2831853071795862f, v));
        float s0, c0;
        safe_sincos(phi, &s0, &c0);
        float nr = __fsub_rn(0.95f, __fmul_rn(0.99f, c0));
        float ni = -__fmul_rn(0.99f, s0);
        float dr = __fsub_rn(1.0f, __fmul_rn(0.9405f, c0));
        float di = -__fmul_rn(0.9405f, s0);
        float inv = 1.0f / (dr * dr + di * di);
        tS_all[idx] = make_float2(0.125f * ((nr * dr + ni * di) * inv),
                                  0.125f * ((ni * dr - nr * di) * inv));
    }

    // Twiddles (per-thread constants, reference-matching f32 angles)
    const float CANG = -0.09817477042468103f;   // fl(-2*pi/64)
    float2 wA[4][3], wB[3];
    #pragma unroll
    for (int e0 = 0; e0 < 4; e0++)
        #pragma unroll
        for (int r = 1; r <= 3; r++) {
            float s0, c0;
            safe_sincos(CANG * (float)((q + 4 * e0) * r), &s0, &c0);
            wA[e0][r - 1] = make_float2(c0, s0);
        }
    #pragma unroll
    for (int s1 = 1; s1 <= 3; s1++) {
        float s0, c0;
        safe_sincos(CANG * (float)(4 * q * s1), &s0, &c0);
        wB[s1 - 1] = make_float2(c0, s0);
    }

    // M = Identity, register-resident: X[e] = M[row, q+4e]
    float2 X[16];
    #pragma unroll
    for (int e = 0; e < 16; e++)
        X[e] = make_float2((q + 4 * e == row) ? 1.0f : 0.0f, 0.0f);

    __syncthreads();    // tS_all visible to all

    // =================== Phase A: build (64 k-steps) ======================
    for (int k = 0; k < Kk; ++k) {
        float2* Ex = (k & 1) ? ExB : ExA;
        const float2* tSb = tS_all + k * Nn;

        // -------- Stage A (stride 16), thread-local ----------------------
        float2 Y[16];
        #pragma unroll
        for (int e0 = 0; e0 < 4; e0++) {
            float2 o0, o1, o2, o3;
            bfly4(X[e0], X[e0 + 4], X[e0 + 8], X[e0 + 12], o0, o1, o2, o3);
            Y[e0]      = o0;
            Y[4 + e0]  = cmul(o1, wA[e0][0]);
            Y[8 + e0]  = cmul(o2, wA[e0][1]);
            Y[12 + e0] = cmul(o3, wA[e0][2]);
        }

        // -------- Stage B (stride 4) -> Ex exchange ----------------------
        #pragma unroll
        for (int r = 0; r < 4; r++) {
            float2 o0, o1, o2, o3;
            bfly4(Y[4 * r + 0], Y[4 * r + 1], Y[4 * r + 2], Y[4 * r + 3],
                  o0, o1, o2, o3);
            int base = row * Sd + q;
            Ex[base + 4 * r]      = o0;                 // s=0
            Ex[base + 16 + 4 * r] = cmul(o1, wB[0]);    // s=1
            Ex[base + 32 + 4 * r] = cmul(o2, wB[1]);    // s=2
            Ex[base + 48 + 4 * r] = cmul(o3, wB[2]);    // s=3
        }
        __syncthreads();

        // -------- Stage C (stride 1, r=q) + diag(t) -> back to X ---------
        #pragma unroll
        for (int s = 0; s < 4; s++) {
            int base = row * Sd + 16 * s + 4 * q;
            float2 o0, o1, o2, o3;
            bfly4(Ex[base + 0], Ex[base + 1], Ex[base + 2], Ex[base + 3],
                  o0, o1, o2, o3);
            int nb = 4 * s + q;
            X[s]      = cmul(o0, tSb[nb]);          // tau=0
            X[4 + s]  = cmul(o1, tSb[nb + 16]);     // tau=1
            X[8 + s]  = cmul(o2, tSb[nb + 32]);     // tau=2
            X[12 + s] = cmul(o3, tSb[nb + 48]);     // tau=3
        }
        // no trailing sync: Ex double-buffered; tS_all read-only
    }
    __syncthreads();   // all stage-C reads done before smem is repurposed

    // ============ M -> SoA planes (Mre, -Mim), stride 66 floats ===========
    float* shf = (float*)sh;
    float* Xr  = shf;                       // [8192] floats (128x64)
    float* Xi  = shf + 8192;                // [8192] floats
    float* Mre = shf + 2 * (2 * Nn * Sd);   // float ofs 16640, 4224 floats
    float* Mim = Mre + Nn * 66;             // 4224 floats (pre-negated)

    #pragma unroll
    for (int e = 0; e < 16; e++) {
        int n = q + 4 * e;
        Mre[row * 66 + n] =  X[e].x;
        Mim[row * 66 + n] = -X[e].y;
    }
    __syncthreads();

    // =================== Phase B: apply (real part only) ==================
    const int tb = tid >> 4;            // 0..15 -> batch rows {8tb..8tb+7}
    const int ti = tid & 15;            // output cols {ti,+16,+32,+48}

    for (int bt = 0; bt < Bb / 128; ++bt) {
        for (int idx = tid; idx < 128 * Nn; idx += 256) {
            int r = idx >> 6, j = idx & 63;
            long long b = (long long)bt * 128 + r;
            long long g = ((b * Dd + d) * Ww + w) * Nn + j;
            Xr[r * 64 + j] = gldf(xr, g * xstride, nxr);
            Xi[r * 64 + j] = gldf(xi, g * xstride, nxi);
        }
        __syncthreads();

        u64t acc[8][4];
        #pragma unroll
        for (int r = 0; r < 8; r++)
            #pragma unroll
            for (int c = 0; c < 4; c++)
                acc[r][c] = 0ull;

        for (int jp = 0; jp < Nn / 2; ++jp) {
            u64t mr2[4], mi2[4];
            #pragma unroll
            for (int c = 0; c < 4; c++) {
                mr2[c] = *(const u64t*)(Mre + (ti + 16 * c) * 66 + 2 * jp);
                mi2[c] = *(const u64t*)(Mim + (ti + 16 * c) * 66 + 2 * jp);
            }
            #pragma unroll
            for (int r = 0; r < 8; r++) {
                u64t xr2 = *(const u64t*)(Xr + (tb * 8 + r) * 64 + 2 * jp);
                u64t xi2 = *(const u64t*)(Xi + (tb * 8 + r) * 64 + 2 * jp);
                #pragma unroll
                for (int c = 0; c < 4; c++) {
                    ffma2(acc[r][c], xr2, mr2[c]);
                    ffma2(acc[r][c], xi2, mi2[c]);   // Mim pre-negated
                }
            }
        }

        #pragma unroll
        for (int r = 0; r < 8; r++)
            #pragma unroll
            for (int c = 0; c < 4; c++) {
                float lo = __uint_as_float((unsigned)(acc[r][c] & 0xffffffffu));
                float hi = __uint_as_float((unsigned)(acc[r][c] >> 32));
                float re = lo + hi;
                long long b = (long long)bt * 128 + tb * 8 + r;
                int i = ti + 16 * c;
                long long g = ((b * Dd + d) * Ww + w) * Nn + i;
                if (g < nof) outf[g] = re;
            }
        __syncthreads();
    }
}

// ---------------------------------------------------------------------------
extern "C" void kernel_launch(void* const* d_in, const int* in_sizes, int n_in,
                              void* d_out, int out_size)
{
    const long long NX = (long long)Bb * Dd * Ww * Nn;   // 33,554,432
    const long long NV = (long long)Kk * Dd * Nn;        // 32,768
    const long long NW = Ww;                             // 128

    const float *x0 = 0, *x1 = 0, *vals = 0, *wls = 0;
    long long nx0 = 0, nx1 = 0, nv = 0, nw = 0;
    int xcomplex = 0;

    for (int pass = 0; pass < 2; ++pass) {
        long long mul = (pass == 0) ? 1 : 4;
        x0 = x1 = vals = wls = 0; nx0 = nx1 = nv = nw = 0; xcomplex = 0;
        int nxbuf = 0;
        for (int i = 0; i < n_in; i++) {
            long long s = (long long)in_sizes[i];
            const float* p = (const float*)d_in[i];
            if (!p) continue;
            if (s == NX * mul) {
                if (nxbuf == 0) { x0 = p; nx0 = NX; nxbuf = 1; }
                else if (nxbuf == 1) { x1 = p; nx1 = NX; nxbuf = 2; }
            } else if (s == 2 * NX * mul) {
                x0 = p; nx0 = 2 * NX; nxbuf = 2; xcomplex = 1;
            } else if (s == NV * mul) { if (!vals) { vals = p; nv = NV; } }
            else if (s == NW * mul)   { if (!wls)  { wls  = p; nw = NW; } }
        }
        if (nxbuf == 1 && vals && wls) {
            xcomplex = 1; nx0 = 2 * NX; x1 = 0; nxbuf = 2;
        }
        if (nxbuf == 2 && vals && wls) break;
        x0 = 0;
    }

    if (!(x0 && vals && wls) || !d_out) {
        long long n = (out_size > 4) ? (long long)out_size / 4 : 1;
        pic_probe<<<(unsigned)((n + 255) / 256), 256>>>((float*)d_out, n);
        return;
    }

    // d_out = out_size float32 (real part) — established R8.
    long long n_floats = ((long long)out_size < NX) ? (long long)out_size : NX;

    const float* xrp; const float* xip; long long nxr, nxi; int xstride;
    if (xcomplex) { xrp = x0; nxr = nx0; xip = x0 + 1; nxi = nx0 - 1; xstride = 2; }
    else          { xrp = x0; nxr = nx0; xip = x1;     nxi = nx1;     xstride = 1; }

    cudaFuncSetAttribute(pic_fused, cudaFuncAttributeMaxDynamicSharedMemorySize,
                         SMEM_BYTES);

    dim3 grid(Ww, Dd);
    pic_fused<<<grid, 256, SMEM_BYTES>>>(vals, nv, wls, nw,
                                         xrp, nxr, xip, nxi, xstride,
                                         (float*)d_out, n_floats);
}